// round 13
// baseline (speedup 1.0000x reference)
#include <cuda_runtime.h>
#include <math.h>

#define NPOS 512
#define NALL 1024
#define DIM  512
#define EPSV 1e-5f
#define COSEPS 1e-8f
#define TILEN 32
#define TILEM 32
#define DK   64            // k-chunk, double-buffered
#define SPADA 68           // A row pad (floats): 272B rows, 16B-aligned
#define SPADB 34           // B row pad (floats): 136B rows, 8B-aligned
#define NTHR 256
#define NCHUNK (DIM / DK)  // 8
#define NEGT 256u          // neg-half blocks
#define NBLK 512u

// smem floats: sA[2][32][68]=4352, sB[2][64][34]=4352, sW[2][64]=128
#define SA_OFF 0
#define SB_OFF 4352
#define SW_OFF 8704
#define SMEM_FLOATS 8832
#define SMEM_BYTES (SMEM_FLOATS * 4)

// ---------------- device scratch ----------------
__device__ float g_rnorm[NALL];
__device__ float g_t1[NPOS];     // t1 + s3 (pos rows)
__device__ float g_t2[NALL];     // t2 + s3 (all rows)
__device__ float g_deno[NPOS];
__device__ float g_total;
__device__ unsigned g_negdone;
__device__ unsigned g_alldone;

__device__ __forceinline__ float warp_sum(float v) {
#pragma unroll
    for (int o = 16; o; o >>= 1) v += __shfl_xor_sync(0xffffffffu, v, o);
    return v;
}

__device__ __forceinline__ float sp(float x) {   // softplus, stable
    return fmaxf(x, 0.f) + log1pf(expf(-fabsf(x)));
}

// ---------------- kernel 1: per-row norm, t1+s3, t2+s3 (+ scratch init) --------
__global__ void row_kernel(const float* __restrict__ pos,
                           const float* __restrict__ neg,
                           const float* __restrict__ w) {
    int row = blockIdx.x;                       // 0..1023
    int t = threadIdx.x;                        // 128
    if (t == 0) {
        if (row < NPOS) g_deno[row] = 0.f;
        if (row == 0) { g_total = 0.f; g_negdone = 0u; g_alldone = 0u; }
    }
    const float* src = (row < NPOS) ? (pos + row * DIM) : (neg + (row - NPOS) * DIM);
    float4 v  = ((const float4*)src)[t];
    float4 u1 = ((const float4*)w)[t];
    float4 u2 = ((const float4*)(w + DIM))[t];
    float4 u3 = ((const float4*)(w + 2 * DIM))[t];
    float ss = v.x * v.x; ss = fmaf(v.y, v.y, ss); ss = fmaf(v.z, v.z, ss); ss = fmaf(v.w, v.w, ss);
    float d1 = v.x * u1.x; d1 = fmaf(v.y, u1.y, d1); d1 = fmaf(v.z, u1.z, d1); d1 = fmaf(v.w, u1.w, d1);
    float d2 = v.x * u2.x; d2 = fmaf(v.y, u2.y, d2); d2 = fmaf(v.z, u2.z, d2); d2 = fmaf(v.w, u2.w, d2);
    float d3 = v.x * u3.x; d3 = fmaf(v.y, u3.y, d3); d3 = fmaf(v.z, u3.z, d3); d3 = fmaf(v.w, u3.w, d3);
    ss = warp_sum(ss); d1 = warp_sum(d1); d2 = warp_sum(d2); d3 = warp_sum(d3);
    __shared__ float red[4][4];
    int wid = t >> 5, lid = t & 31;
    if (lid == 0) { red[0][wid] = ss; red[1][wid] = d1; red[2][wid] = d2; red[3][wid] = d3; }
    __syncthreads();
    if (t == 0) {
        float S  = red[0][0] + red[0][1] + red[0][2] + red[0][3];
        float D1 = red[1][0] + red[1][1] + red[1][2] + red[1][3];
        float D2 = red[2][0] + red[2][1] + red[2][2] + red[2][3];
        float D3 = red[3][0] + red[3][1] + red[3][2] + red[3][3];
        g_rnorm[row] = 1.f / fmaxf(sqrtf(S), COSEPS);
        g_t2[row] = D2 + D3;                    // t2 + s3
        if (row < NPOS) g_t1[row] = D1 + D3;    // t1 + s3
    }
}

// ---------------- kernel 2: fused pair kernel ----------------
// grid (32, 16): bx<16 -> pos-vs-pos (loss1 + bce), bx>=16 -> pos-vs-neg (deno + bce)
// 256 threads, 4 CTAs/SM (8 warps/SMSP), 2n x 2m micro-tile, DK=64 double buffer,
// store-immediately prefetch (prefetch regs freed before compute).
__global__ void __launch_bounds__(NTHR, 4) pair_kernel(
    const float* __restrict__ pos, const float* __restrict__ neg,
    const float* __restrict__ w, const float* __restrict__ bptr,
    float* __restrict__ out)
{
    extern __shared__ float smem[];
    float (*sA)[TILEN][SPADA] = (float (*)[TILEN][SPADA])(smem + SA_OFF); // [buf][row][d]
    float (*sB)[DK][SPADB]    = (float (*)[DK][SPADB])(smem + SB_OFF);    // [buf][d][col]
    float (*sW)[DK]           = (float (*)[DK])(smem + SW_OFF);
    __shared__ float sRed[8];

    const int t  = threadIdx.x;
    const int tx = t & 15;           // m: 2 cols each (2tx, 2tx+1)
    const int ty = t >> 4;           // n: 2 rows each (2ty, 2ty+1), 0..15
    const int n0 = blockIdx.y * TILEN;
    const int m0 = blockIdx.x * TILEM;
    const bool pos_half = (m0 < NPOS);
    const float* Bsrc = pos_half ? pos : neg;
    const int mrow0 = pos_half ? m0 : (m0 - NPOS);
    const float* w3 = w + 2 * DIM;

    float dotv[2][2], mnv[2][2];
#pragma unroll
    for (int i = 0; i < 2; i++)
#pragma unroll
        for (int j = 0; j < 2; j++) { dotv[i][j] = 0.f; mnv[i][j] = 0.f; }

    // A loader: arow = t>>3 (0..31), 8 floats at (t&7)*8
    const int arow = t >> 3;
    const int adq  = (t & 7) * 8;
    // B loader: lc = d (0..63), rows lr+4q (q<8)
    const int lc = t & 63;
    const int lr = t >> 6;

    // load global chunk -> immediately store to smem buffer (short pf live range;
    // the LDG->STS stall is covered by the other CTAs'/warps' compute)
#define LOADSTORE(Dz, buf) do {                                            \
    float4 xa0 = *(const float4*)(pos + (n0 + arow) * DIM + (Dz) + adq);   \
    float4 xa1 = *(const float4*)(pos + (n0 + arow) * DIM + (Dz) + adq + 4);\
    float xb[8];                                                           \
    _Pragma("unroll")                                                      \
    for (int q = 0; q < 8; q++)                                            \
        xb[q] = Bsrc[(mrow0 + lr + 4 * q) * DIM + (Dz) + lc];              \
    float4 xw;                                                             \
    if (t < 16) xw = *(const float4*)(w3 + (Dz) + t * 4);                  \
    *(float4*)&sA[buf][arow][adq]     = xa0;                               \
    *(float4*)&sA[buf][arow][adq + 4] = xa1;                               \
    _Pragma("unroll")                                                      \
    for (int q = 0; q < 8; q++)                                            \
        sB[buf][lc][lr + 4 * q] = xb[q];                                   \
    if (t < 16) *(float4*)&sW[buf][t * 4] = xw;                            \
} while (0)

    LOADSTORE(0, 0);
    __syncthreads();

    for (int c = 0; c < NCHUNK; c++) {
        const int cur = c & 1;
        if (c < NCHUNK - 1) LOADSTORE((c + 1) * DK, 1 - cur);

#pragma unroll 4
        for (int kg = 0; kg < DK / 4; kg++) {      // 16 groups of 4 kk
            const float4 wv4 = *(const float4*)&sW[cur][kg * 4];
            const float4 a0v = *(const float4*)&sA[cur][ty * 2]    [kg * 4];
            const float4 a1v = *(const float4*)&sA[cur][ty * 2 + 1][kg * 4];
            const float aw[2][4] = {{a0v.x, a0v.y, a0v.z, a0v.w},
                                    {a1v.x, a1v.y, a1v.z, a1v.w}};
            const float wk[4] = {wv4.x, wv4.y, wv4.z, wv4.w};
#pragma unroll
            for (int u = 0; u < 4; u++) {
                float2 bv = *(const float2*)&sB[cur][kg * 4 + u][tx * 2];
                float b[2] = {bv.x, bv.y};
#pragma unroll
                for (int i = 0; i < 2; i++)
#pragma unroll
                    for (int j = 0; j < 2; j++) {
                        dotv[i][j] = fmaf(aw[i][u], b[j], dotv[i][j]);
                        mnv[i][j]  = fmaf(fminf(aw[i][u], b[j]), wk[u], mnv[i][j]);
                    }
            }
        }
        __syncthreads();
    }

    // ---- epilogue ----
    int gn[2];
    float rn_n[2], t1v[2], rn_m[2], t2v[2];
#pragma unroll
    for (int i = 0; i < 2; i++) {
        gn[i] = n0 + ty * 2 + i;
        rn_n[i] = g_rnorm[gn[i]];
        t1v[i]  = g_t1[gn[i]];     // includes s3[n]
    }
#pragma unroll
    for (int j = 0; j < 2; j++) {
        int gm = m0 + tx * 2 + j;
        rn_m[j] = g_rnorm[gm];
        t2v[j]  = g_t2[gm];        // includes s3[m]
    }
    float bias = __ldg(bptr);

    float part = 0.f;

    if (!pos_half) {
        // ---- negative half: bce(label 0) + deno ----
        float bce = 0.f, dl[2] = {0.f, 0.f};
#pragma unroll
        for (int i = 0; i < 2; i++) {
#pragma unroll
            for (int j = 0; j < 2; j++) {
                float cc = dotv[i][j] * rn_n[i] * rn_m[j];
                float logit = t1v[i] + t2v[j] - 2.f * mnv[i][j] + bias;
                bce += sp(logit);
                dl[i] += expf(cc);
            }
        }
        // reduce across the 16 tx-lanes sharing each n-row (bits 0..3 of lane)
#pragma unroll
        for (int i = 0; i < 2; i++) {
            float v = dl[i];
            v += __shfl_xor_sync(0xffffffffu, v, 1);
            v += __shfl_xor_sync(0xffffffffu, v, 2);
            v += __shfl_xor_sync(0xffffffffu, v, 4);
            v += __shfl_xor_sync(0xffffffffu, v, 8);
            if (tx == 0) atomicAdd(&g_deno[gn[i]], v);
        }
        __threadfence();                       // publish deno before negdone arrive
        part = bce * (1.0f / (float)NALL);
    } else {
        // ---- positive half: wait for deno, then bce(label 1) + contrastive ----
        if (t == 0) {
            while (atomicCAS(&g_negdone, NEGT, NEGT) != NEGT) { __nanosleep(200); }
        }
        __syncthreads();
        __threadfence();
        float dn[2];
#pragma unroll
        for (int i = 0; i < 2; i++) dn[i] = __ldcg(&g_deno[gn[i]]);

        float bce = 0.f, l1 = 0.f;
#pragma unroll
        for (int i = 0; i < 2; i++) {
#pragma unroll
            for (int j = 0; j < 2; j++) {
                float cc = dotv[i][j] * rn_n[i] * rn_m[j];
                float logit = t1v[i] + t2v[j] - 2.f * mnv[i][j] + bias;
                bce += sp(-logit);
                l1 += logf(dn[i] + expf(cc) + EPSV) - cc;  // -log(e^c/(deno+e^c+eps))
            }
        }
        part = bce * (1.0f / (float)NALL) + l1;
    }

    // ---- block reduce + global accumulate + completion protocol ----
    float v = warp_sum(part);
    if ((t & 31) == 0) sRed[t >> 5] = v;
    __syncthreads();
    if (t == 0) {
        float s = 0.f;
#pragma unroll
        for (int k = 0; k < 8; k++) s += sRed[k];
        atomicAdd(&g_total, s);
        __threadfence();
        if (!pos_half) atomicAdd(&g_negdone, 1u);
        unsigned old = atomicAdd(&g_alldone, 1u);
        if (old == NBLK - 1u) {
            __threadfence();
            out[0] = atomicAdd(&g_total, 0.f);
        }
    }
}

// ---------------- launch ----------------
extern "C" void kernel_launch(void* const* d_in, const int* in_sizes, int n_in,
                              void* d_out, int out_size) {
    const float* pos = (const float*)d_in[0];   // [512,512]
    const float* neg = (const float*)d_in[1];   // [512,512]
    const float* w   = (const float*)d_in[2];   // [1,1536]
    const float* b   = (const float*)d_in[3];   // [1]
    float* out = (float*)d_out;

    cudaFuncSetAttribute(pair_kernel,
                         cudaFuncAttributeMaxDynamicSharedMemorySize, SMEM_BYTES);

    row_kernel<<<NALL, 128>>>(pos, neg, w);
    dim3 grid(NALL / TILEM, NPOS / TILEN);      // (32, 16) = 512 blocks, 4/SM, one wave
    pair_kernel<<<grid, NTHR, SMEM_BYTES>>>(pos, neg, w, b, out);
}